// round 17
// baseline (speedup 1.0000x reference)
#include <cuda_runtime.h>
#include <cuda_bf16.h>
#include <cstdint>

// Problem constants
#define BB 128
#define SS 512
#define UU 1024
#define TT 48

#define KCH 16            // floats per k-chunk (one k16 mma step)
#define NCH (UU / KCH)    // 64 chunks
#define STG 4             // cp.async pipeline stages
#define RSTRIDE 20        // smem row stride in floats (pad: 2-way max conflicts)

// Scratch (device globals — no runtime allocation)
__device__ float g_scores[BB * SS * TT];            // fp32 scores, 12.6 MB
// W pre-baked into mma.sync B-fragment layout:
// [s2 (32)][j (6)][lane (32)] uint4 = {b0,b1 of k-step 2*s2, b0,b1 of 2*s2+1}
__device__ __align__(16) uint4 g_Wfrag[32 * 6 * 32];

__device__ __forceinline__ uint32_t smem_u32(const void* p) {
    uint32_t a;
    asm("{ .reg .u64 t; cvta.to.shared.u64 t, %1; cvt.u32.u64 %0, t; }"
        : "=r"(a) : "l"(p));
    return a;
}
__device__ __forceinline__ uint32_t packbf(float2 f) {
    __nv_bfloat162 h = __float22bfloat162_rn(f);
    return *reinterpret_cast<uint32_t*>(&h);
}
__device__ __forceinline__ void mma16816(float d[4],
                                         uint32_t a0, uint32_t a1,
                                         uint32_t a2, uint32_t a3,
                                         uint32_t b0, uint32_t b1) {
    asm volatile(
        "mma.sync.aligned.m16n8k16.row.col.f32.bf16.bf16.f32 "
        "{%0,%1,%2,%3}, {%4,%5,%6,%7}, {%8,%9}, {%0,%1,%2,%3};"
        : "+f"(d[0]), "+f"(d[1]), "+f"(d[2]), "+f"(d[3])
        : "r"(a0), "r"(a1), "r"(a2), "r"(a3), "r"(b0), "r"(b1));
}
__device__ __forceinline__ void cp16(uint32_t dst, const void* src) {
    asm volatile("cp.async.cg.shared.global [%0], [%1], 16;"
                 :: "r"(dst), "l"(src) : "memory");
}
#define CP_COMMIT() asm volatile("cp.async.commit_group;" ::: "memory")
#define CP_WAIT(n)  asm volatile("cp.async.wait_group %0;" :: "n"(n) : "memory")
#define BAR_FWD()   asm volatile("bar.sync 1, 64;" ::: "memory")
#define BAR_BWD()   asm volatile("bar.sync 2, 64;" ::: "memory")

// ---------------------------------------------------------------------------
// One-shot: bake W [U][T] into B fragments (bf16) for mma.sync.
// ---------------------------------------------------------------------------
__global__ void wfrag_kernel(const float* __restrict__ W) {
    int idx = blockIdx.x * 256 + threadIdx.x;     // 0 .. 64*6*32-1
    if (idx >= 64 * 6 * 32) return;
    int lane = idx & 31;
    int j    = (idx >> 5) % 6;
    int s    = idx / (6 * 32);                    // k-step 0..63
    int c    = lane & 3;
    int n    = 8 * j + (lane >> 2);
    int k0   = 16 * s + 2 * c;
    uint32_t b0 = packbf(make_float2(W[(size_t)k0 * TT + n],
                                     W[(size_t)(k0 + 1) * TT + n]));
    uint32_t b1 = packbf(make_float2(W[(size_t)(k0 + 8) * TT + n],
                                     W[(size_t)(k0 + 9) * TT + n]));
    int s2 = s >> 1, h = s & 1;
    uint32_t* out = reinterpret_cast<uint32_t*>(&g_Wfrag[(s2 * 6 + j) * 32 + lane]);
    out[h * 2 + 0] = b0;
    out[h * 2 + 1] = b1;
}

// ---------------------------------------------------------------------------
// GEMM via mma.sync bf16 + cp.async 4-stage smem pipeline (R12-exact, 75us).
// ---------------------------------------------------------------------------
__global__ __launch_bounds__(256)
void gemm_mma(const float* __restrict__ H, const float* __restrict__ bias) {
    __shared__ __align__(16) float sA[STG * 128 * RSTRIDE];   // 40 KB

    const int tid  = threadIdx.x;
    const int w    = tid >> 5;
    const int lane = tid & 31;
    const int c    = lane & 3;
    const int g    = lane >> 2;

    const int crow  = tid >> 1;
    const int chalf = tid & 1;
    const float* gsrc = H + ((size_t)blockIdx.x * 128 + crow) * UU + chalf * 8;
    const uint32_t sbase = smem_u32(sA);
    const uint32_t cdst  = sbase + (crow * RSTRIDE + chalf * 8) * 4;

    const size_t m0 = (size_t)blockIdx.x * 128 + w * 16;
    const float* srow = sA + (w * 16 + g) * RSTRIDE + 2 * c;

    float2 bias2[6];
#pragma unroll
    for (int j = 0; j < 6; j++)
        bias2[j] = *reinterpret_cast<const float2*>(bias + 8 * j + 2 * c);

    float d[6][4];
#pragma unroll
    for (int j = 0; j < 6; j++)
#pragma unroll
        for (int i = 0; i < 4; i++) d[j][i] = 0.f;

#pragma unroll
    for (int ch = 0; ch < 3; ch++) {
        uint32_t dst = cdst + ch * (128 * RSTRIDE * 4);
        const float* src = gsrc + ch * KCH;
        cp16(dst, src);
        cp16(dst + 16, src + 4);
        CP_COMMIT();
    }

    for (int s2 = 0; s2 < 32; s2++) {
        uint4 bf[6];
        {
            const uint4* bp = g_Wfrag + (size_t)(s2 * 6) * 32 + lane;
#pragma unroll
            for (int j = 0; j < 6; j++) bf[j] = bp[j * 32];
        }
        {
            const int ch = 2 * s2;
            if (ch < NCH - 2) { CP_WAIT(2); } else { CP_WAIT(0); }
            __syncthreads();
            if (ch + 3 < NCH) {
                uint32_t dst = cdst + ((ch + 3) & 3) * (128 * RSTRIDE * 4);
                const float* src = gsrc + (ch + 3) * KCH;
                cp16(dst, src);
                cp16(dst + 16, src + 4);
                CP_COMMIT();
            }
            const float* sp = srow + (ch & 3) * (128 * RSTRIDE);
            float2 f0 = *reinterpret_cast<const float2*>(sp);
            float2 f1 = *reinterpret_cast<const float2*>(sp + 8 * RSTRIDE);
            float2 f2 = *reinterpret_cast<const float2*>(sp + 8);
            float2 f3 = *reinterpret_cast<const float2*>(sp + 8 * RSTRIDE + 8);
            uint32_t a0 = packbf(f0), a1 = packbf(f1);
            uint32_t a2 = packbf(f2), a3 = packbf(f3);
#pragma unroll
            for (int j = 0; j < 6; j++)
                mma16816(d[j], a0, a1, a2, a3, bf[j].x, bf[j].y);
        }
        {
            const int ch = 2 * s2 + 1;
            if (ch < NCH - 2) { CP_WAIT(2); } else { CP_WAIT(0); }
            __syncthreads();
            if (ch + 3 < NCH) {
                uint32_t dst = cdst + ((ch + 3) & 3) * (128 * RSTRIDE * 4);
                const float* src = gsrc + (ch + 3) * KCH;
                cp16(dst, src);
                cp16(dst + 16, src + 4);
                CP_COMMIT();
            }
            const float* sp = srow + (ch & 3) * (128 * RSTRIDE);
            float2 f0 = *reinterpret_cast<const float2*>(sp);
            float2 f1 = *reinterpret_cast<const float2*>(sp + 8 * RSTRIDE);
            float2 f2 = *reinterpret_cast<const float2*>(sp + 8);
            float2 f3 = *reinterpret_cast<const float2*>(sp + 8 * RSTRIDE + 8);
            uint32_t a0 = packbf(f0), a1 = packbf(f1);
            uint32_t a2 = packbf(f2), a3 = packbf(f3);
#pragma unroll
            for (int j = 0; j < 6; j++)
                mma16816(d[j], a0, a1, a2, a3, bf[j].z, bf[j].w);
        }
    }

    float* dst0 = g_scores + (m0 + g) * TT;
    float* dst1 = dst0 + 8 * TT;
#pragma unroll
    for (int j = 0; j < 6; j++) {
        *reinterpret_cast<float2*>(dst0 + 8 * j + 2 * c) =
            make_float2(d[j][0] + bias2[j].x, d[j][1] + bias2[j].y);
        *reinterpret_cast<float2*>(dst1 + 8 * j + 2 * c) =
            make_float2(d[j][2] + bias2[j].x, d[j][3] + bias2[j].y);
    }
}

// 48-element dot of E[] (regs) with vec (smem, float4, broadcast), 4 accums
__device__ __forceinline__ float dot48(const float* E, const float* vec,
                                       float& first) {
    const float4* vp = reinterpret_cast<const float4*>(vec);
    float4 q0 = vp[0];
    first = q0.x;
    float a0 = q0.x * E[0], a1 = q0.y * E[1];
    float a2 = q0.z * E[2], a3 = q0.w * E[3];
#pragma unroll
    for (int j = 1; j < 12; j++) {
        float4 q = vp[j];
        a0 = fmaf(q.x, E[4 * j + 0], a0);
        a1 = fmaf(q.y, E[4 * j + 1], a1);
        a2 = fmaf(q.z, E[4 * j + 2], a2);
        a3 = fmaf(q.w, E[4 * j + 3], a3);
    }
    return (a0 + a1) + (a2 + a3);
}

// ---------------------------------------------------------------------------
// Bidirectional scan, TWO WARPS PER DIRECTION + numerator. 160 threads:
//   warps 0-1: forward alpha scan, m=(len-1)/2 steps. Warp q owns states
//              [24q,24q+24); lane<24 owns one state (48 FMA/step — half of
//              R16's 96); per-step sync = named barrier `bar.sync 1,64`.
//   warps 2-3: backward beta scan, K=len-1-m steps, `bar.sync 2,64`.
//   warp 4   : numerator.
// Single final __syncthreads joins all; thread 0 combines.
// logZ = (Cf+Cb)·ln2 + log(sum_t alpha_m[t]·beta_m[t]);  out = num - logZ.
// ---------------------------------------------------------------------------
__global__ __launch_bounds__(160, 1)
void scan_kernel(const float* __restrict__ trans,
                 const float* __restrict__ startT,
                 const float* __restrict__ endT,
                 const int* __restrict__ tag,
                 const int* __restrict__ s_len,
                 float* __restrict__ out) {
    const int b   = blockIdx.x;
    const int tid = threadIdx.x;
    const int wid = tid >> 5;
    const int l   = tid & 31;
    __shared__ __align__(16) float vf[2][48];
    __shared__ __align__(16) float vb[2][48];
    __shared__ float redf[48];
    __shared__ float redb[48];
    __shared__ float s_num;
    __shared__ int   s_CeB;

    const int len = s_len[b];
    const int m   = (len - 1) >> 1;      // meeting point
    const int K   = len - 1 - m;
    const float* sc = g_scores + (size_t)b * SS * TT;

    if (wid < 2) {
        // ---------------- FORWARD warps 0,1: lane owns state 24*wid+l ------
        const bool act = l < 24;
        const int st = act ? 24 * wid + l : 0;

        float E[TT];
#pragma unroll
        for (int k = 0; k < TT; k++) {
            float e = __expf(trans[k * TT + st]);   // column st
            E[k] = act ? e : 0.f;
        }
        float af = act ? __expf(startT[st] + sc[st]) : 0.f;   // alpha_0
        if (act) vf[0][st] = af;
        int Ce = 0;

        float x1 = __expf(sc[1 * TT + st]);
        float eA = sc[2 * TT + st];
        float eB = sc[3 * TT + st];
        BAR_FWD();

        int cur = 0;
        for (int i = 0; i < m; ++i) {
            const int s = i + 1;
            float ex = x1;
            x1 = __expf(eA); eA = eB;
            int sp = s + 3; if (sp > SS - 1) sp = SS - 1;
            eB = sc[sp * TT + st];

            float v0;
            float dot = dot48(E, vf[cur], v0);

            int eb = (__float_as_int(v0) >> 23) & 0xff;
            Ce += eb - 127;
            float sx = __int_as_float((254 - eb) << 23) * ex;
            af = dot * sx;

            if (act) vf[cur ^ 1][st] = af;
            BAR_FWD();
            cur ^= 1;
        }
        if (act) redf[st] = af;
        __syncthreads();                               // single block barrier

        if (tid == 0) {
            float ssum = 0.f;
#pragma unroll
            for (int k = 0; k < TT; k++) ssum += redf[k] * redb[k];
            float logZ = (float)(Ce + s_CeB) * 0.6931471805599453f + __logf(ssum);
            out[b] = s_num - logZ;
        }
    } else if (wid < 4) {
        // ---------------- BACKWARD warps 2,3: lane owns state 24*(wid-2)+l -
        const bool act = l < 24;
        const int st = act ? 24 * (wid - 2) + l : 0;

        float E[TT];
#pragma unroll
        for (int k = 0; k < TT; k++) {
            float e = __expf(trans[st * TT + k]);   // row st
            E[k] = act ? e : 0.f;
        }
        // init w_{len-1} = exp(emit_{len-1} + end)
        float bw = act ? __expf(sc[(size_t)(len - 1) * TT + st] + endT[st]) : 0.f;
        if (act) vb[0][st] = bw;
        int Ce = 0;

        int q1 = len - 2; if (q1 < 0) q1 = 0;
        int q2 = len - 3; if (q2 < 0) q2 = 0;
        int q3 = len - 4; if (q3 < 0) q3 = 0;
        float x1 = __expf(sc[(size_t)q1 * TT + st]);
        float eA = sc[(size_t)q2 * TT + st];
        float eB = sc[(size_t)q3 * TT + st];
        BAR_BWD();

        int cur = 0;
        for (int i = 0; i < K; ++i) {
            const int s = len - 2 - i;                 // s: len-2 .. m
            float ex = x1;
            x1 = __expf(eA); eA = eB;
            int sp = s - 3; if (sp < 0) sp = 0;
            eB = sc[(size_t)sp * TT + st];

            float w0;
            float dot = dot48(E, vb[cur], w0);         // b_s[st] = E_row · w_{s+1}

            int eb = (__float_as_int(w0) >> 23) & 0xff;
            Ce += eb - 127;
            float scl = __int_as_float((254 - eb) << 23);
            bw = (s > m) ? (dot * scl * ex) : (dot * scl);

            if (act) vb[cur ^ 1][st] = bw;
            BAR_BWD();
            cur ^= 1;
        }
        if (K == 0) bw = act ? __expf(endT[st]) : 0.f;   // len==1
        if (act) redb[st] = bw;
        if (wid == 2 && l == 0) s_CeB = Ce;
        __syncthreads();                               // single block barrier
    } else {
        // ---------------- numerator warp (wid 4) ----------------
        const int* tg = tag + b * SS;
        float local = 0.f;
        for (int s = l; s < len; s += 32) {
            int tc2 = tg[s];
            local += sc[s * TT + tc2];
            if (s >= 1) local += trans[tg[s - 1] * TT + tc2];
        }
        if (l == 0) local += startT[tg[0]] + endT[tg[len - 1]];
#pragma unroll
        for (int o = 16; o > 0; o >>= 1)
            local += __shfl_down_sync(0xffffffffu, local, o);
        if (l == 0) s_num = local;
        __syncthreads();                               // single block barrier
    }
}

// ---------------------------------------------------------------------------
// Launch. Inputs: H, W, b, start_transitions, end_transitions, transitions,
// tag(int32), s_len(int32), w_mask (unused: mask == s < s_len).
// ---------------------------------------------------------------------------
extern "C" void kernel_launch(void* const* d_in, const int* in_sizes, int n_in,
                              void* d_out, int out_size) {
    const float* H      = (const float*)d_in[0];
    const float* W      = (const float*)d_in[1];
    const float* bias   = (const float*)d_in[2];
    const float* startT = (const float*)d_in[3];
    const float* endT   = (const float*)d_in[4];
    const float* trans  = (const float*)d_in[5];
    const int*   tag    = (const int*)d_in[6];
    const int*   s_len  = (const int*)d_in[7];
    (void)in_sizes; (void)n_in; (void)out_size;
    float* out = (float*)d_out;

    wfrag_kernel<<<48, 256>>>(W);
    gemm_mma<<<(BB * SS) / 128, 256>>>(H, bias);
    scan_kernel<<<BB, 160>>>(trans, startT, endT, tag, s_len, out);
}